// round 10
// baseline (speedup 1.0000x reference)
#include <cuda_runtime.h>
#include <cstdint>

#define THREADS 256
#define NCH 12              // 768 / 64 floats per chunk
#define NP1 1369

// ---- smem float offsets ----
#define AOF 0               // A stages: 3 * 2448 floats (36 rows x 68)
#define BOF 7344            // B stages: 3 * 2448 floats
#define GWF 14688           // g*w vector, 768
#define WPF 15456           // 8 warps * 2
#define STF 15472           // stats partials 144*3 = 432
#define RNF 15904           // rsqrt norms 72
#define DUF 15976           // dustbin*10 72
#define UF  16048
#define VF  16085
#define EUF 16122
#define EVF 16159
#define TOTF 16196
#define SM_FLOATS 16224
#define SM_BYTES (SM_FLOATS*4)   // 64896
// post-loop aliases (A stages dead after main loop)
#define CSF 0               // couplings 1369  (A stages 0-1)
#define ECF 4896            // exp couplings 1369 (A stage 2)

#define NORMC (-4.27666611901605529f)   // -log(72)
#define LMD   (-0.69314718055994531f)   // log(36)-log(72)

__device__ __forceinline__ void fma2(unsigned long long &d,
                                     unsigned long long a,
                                     unsigned long long b) {
    asm volatile("fma.rn.f32x2 %0, %1, %2, %0;" : "+l"(d) : "l"(a), "l"(b));
}
__device__ __forceinline__ float lo32(unsigned long long a){ return __uint_as_float((unsigned)a); }
__device__ __forceinline__ float hi32(unsigned long long a){ return __uint_as_float((unsigned)(a>>32)); }

__device__ __forceinline__ uint32_t f2tf(float f) {
    uint32_t u; asm("cvt.rna.tf32.f32 %0, %1;" : "=r"(u) : "f"(f)); return u;
}
__device__ __forceinline__ void mma1688(float* d, const uint32_t* a, const uint32_t* b) {
    asm volatile(
        "mma.sync.aligned.m16n8k8.row.col.f32.tf32.tf32.f32 "
        "{%0,%1,%2,%3}, {%4,%5,%6,%7}, {%8,%9}, {%0,%1,%2,%3};"
        : "+f"(d[0]), "+f"(d[1]), "+f"(d[2]), "+f"(d[3])
        : "r"(a[0]), "r"(a[1]), "r"(a[2]), "r"(a[3]), "r"(b[0]), "r"(b[1]));
}
__device__ __forceinline__ void cp16(uint32_t dst, const float* src) {
    asm volatile("cp.async.cg.shared.global [%0], [%1], 16;"
                 :: "r"(dst), "l"(src) : "memory");
}

// one 72-row x 64-float chunk: x rows -> A stage, y rows -> B stage
__device__ __forceinline__ void load_chunk(uint32_t smb, const float* xb,
                                           const float* yb, int c, int t) {
    uint32_t sA = smb + AOF*4 + (c%3)*9792;
    uint32_t sB = smb + BOF*4 + (c%3)*9792;
    #pragma unroll
    for (int r = 0; r < 5; ++r) {
        int op = t + THREADS*r;          // 0..1279; 1152 used
        if (op < 1152) {
            int row = op >> 4, c4 = op & 15;
            if (row < 36)
                cp16(sA + row*272 + c4*16, xb + row*768 + c*64 + c4*4);
            else
                cp16(sB + (row-36)*272 + c4*16, yb + (row-36)*768 + c*64 + c4*4);
        }
    }
    asm volatile("cp.async.commit_group;" ::: "memory");
}

// ======================= fused kernel ===================================
__global__ void __launch_bounds__(THREADS, 3)
k_fused(const float* __restrict__ X, const float* __restrict__ Y,
        const float* __restrict__ G, const float* __restrict__ Bln,
        const float* __restrict__ W, const float* __restrict__ Blin,
        float* __restrict__ out, int B)
{
    extern __shared__ __align__(16) float smf[];
    uint32_t smb;
    asm("{ .reg .u64 tt; cvta.to.shared.u64 tt, %1; cvt.u32.u64 %0, tt; }"
        : "=r"(smb) : "l"(smf));
    const int t = threadIdx.x;
    const int w = t >> 5, lid = t & 31;
    const int g = lid >> 2, tig = lid & 3;
    const int b = blockIdx.x;
    const float* xb = X + (size_t)b * 27648;
    const float* yb = Y + (size_t)b * 27648;

    // prefetch chunks 0,1
    load_chunk(smb, xb, yb, 0, t);
    load_chunk(smb, xb, yb, 1, t);

    // g*w vector + warp partials
    {
        float sgw = 0.f, sbw = 0.f;
        for (int h = t; h < 768; h += THREADS) {
            float wv = W[h];
            float gv = G[h]*wv;
            smf[GWF + h] = gv;
            sgw += gv;
            sbw += Bln[h]*wv;
        }
        #pragma unroll
        for (int o = 16; o > 0; o >>= 1) {
            sgw += __shfl_down_sync(0xffffffffu, sgw, o);
            sbw += __shfl_down_sync(0xffffffffu, sbw, o);
        }
        if (lid == 0) { smf[WPF + w*2] = sgw; smf[WPF + w*2 + 1] = sbw; }
    }

    // GEMM: warps 0-5.  mt row-bases {0,16,20}; n col-bases nh0:{0,8,16} nh1:{24,28}
    // overlapped tiles recompute identical values (benign duplicate writes)
    const int mt  = w >> 1;
    const int nh  = w & 1;
    const int row0 = (mt < 2) ? mt*16 : 20;
    const int ntn = nh ? 2 : 3;
    float acc[3][4];
    #pragma unroll
    for (int j = 0; j < 3; ++j)
        #pragma unroll
        for (int e = 0; e < 4; ++e) acc[j][e] = 0.f;

    // stats: warps 6-7
    const int t2 = t - 192;
    unsigned long long sx2[3] = {0,0,0}, sxx2[3] = {0,0,0}, sxg2[3] = {0,0,0};
    const unsigned long long ONES2 = 0x3f8000003f800000ULL;

    #pragma unroll 1
    for (int c = 0; c < NCH; ++c) {
        if (c < NCH-1) asm volatile("cp.async.wait_group 1;" ::: "memory");
        else           asm volatile("cp.async.wait_group 0;" ::: "memory");
        __syncthreads();
        if (c + 2 < NCH) load_chunk(smb, xb, yb, c+2, t);

        if (w < 6) {
            // k-slot pairing: slot tig <- smem pos 2*tig, slot tig+4 <- pos 2*tig+1
            // (k-permutation, identical for A and B -> dot product unchanged)
            const float* As = smf + AOF + (c%3)*2448 + (row0 + g)*68 + tig*2;
            const float* Bs = smf + BOF + (c%3)*2448 + g*68 + tig*2
                              + (nh ? 24*68 : 0);
            #pragma unroll
            for (int ks = 0; ks < 8; ++ks) {
                const int ko = ks*8;
                float2 a01 = *reinterpret_cast<const float2*>(As + ko);
                float2 a23 = *reinterpret_cast<const float2*>(As + 8*68 + ko);
                uint32_t a[4];
                a[0] = f2tf(a01.x);
                a[1] = f2tf(a23.x);
                a[2] = f2tf(a01.y);
                a[3] = f2tf(a23.y);
                #pragma unroll
                for (int j = 0; j < 3; ++j) {
                    if (j < ntn) {
                        // col base: nh0 -> j*8; nh1 -> 24 + j*4
                        float2 bb = *reinterpret_cast<const float2*>(
                            Bs + (nh ? j*4*68 : j*8*68) + ko);
                        uint32_t bf[2];
                        bf[0] = f2tf(bb.x);
                        bf[1] = f2tf(bb.y);
                        mma1688(acc[j], a, bf);
                    }
                }
            }
        } else {
            #pragma unroll
            for (int sl = 0; sl < 3; ++sl) {
                int s = t2 + sl*64;
                if (sl < 2 || t2 < 16) {
                    int srow = s >> 1, half = s & 1;
                    const float* rp = smf + (srow < 36
                        ? AOF + (c%3)*2448 + srow*68
                        : BOF + (c%3)*2448 + (srow-36)*68) + half*32;
                    const float* gp = smf + GWF + c*64 + half*32;
                    #pragma unroll
                    for (int j = 0; j < 8; ++j) {
                        ulonglong2 v  = *reinterpret_cast<const ulonglong2*>(rp + j*4);
                        ulonglong2 gg = *reinterpret_cast<const ulonglong2*>(gp + j*4);
                        fma2(sx2[sl],  v.x, ONES2);  fma2(sx2[sl],  v.y, ONES2);
                        fma2(sxx2[sl], v.x, v.x);    fma2(sxx2[sl], v.y, v.y);
                        fma2(sxg2[sl], v.x, gg.x);   fma2(sxg2[sl], v.y, gg.y);
                    }
                }
            }
        }
    }

    if (t2 >= 0) {
        #pragma unroll
        for (int sl = 0; sl < 3; ++sl) {
            int s = t2 + sl*64;
            if (sl < 2 || t2 < 16) {
                smf[STF + s*3 + 0] = lo32(sx2[sl])  + hi32(sx2[sl]);
                smf[STF + s*3 + 1] = lo32(sxx2[sl]) + hi32(sxx2[sl]);
                smf[STF + s*3 + 2] = lo32(sxg2[sl]) + hi32(sxg2[sl]);
            }
        }
    }
    __syncthreads();    // main loop done; stage buffers dead -> aliases live

    // per-row finalize (72 rows)
    if (t < 72) {
        float Sx  = smf[STF + (2*t)*3 + 0] + smf[STF + (2*t+1)*3 + 0];
        float Sxx = smf[STF + (2*t)*3 + 1] + smf[STF + (2*t+1)*3 + 1];
        float Sxg = smf[STF + (2*t)*3 + 2] + smf[STF + (2*t+1)*3 + 2];
        float Sgw = 0.f, Sbw = 0.f;
        #pragma unroll
        for (int j = 0; j < 8; ++j) {
            Sgw += smf[WPF + j*2 + 0];
            Sbw += smf[WPF + j*2 + 1];
        }
        smf[RNF + t] = rsqrtf(Sxx);
        float mu  = Sx * (1.f/768.f);
        float var = Sxx * (1.f/768.f) - mu*mu;
        float rsd = rsqrtf(var + 1e-5f);
        smf[DUF + t] = tanhf((Sxg - mu*Sgw)*rsd + Sbw + Blin[0]) * 10.f;
    }
    if (t < 37) {
        smf[UF + t] = 0.f; smf[VF + t] = 0.f;
        smf[EUF + t] = 1.f; smf[EVF + t] = 1.f;
    }
    if (t == 0) smf[TOTF] = 0.f;
    __syncthreads();

    // write scaled couplings from MMA accumulators (duplicates benign)
    if (w < 6) {
        #pragma unroll
        for (int j = 0; j < 3; ++j) {
            if (j < ntn) {
                int r0 = row0 + g;
                int c0 = (nh ? 24 + j*4 : j*8) + 2*tig;
                #pragma unroll
                for (int e = 0; e < 4; ++e) {
                    int rr = r0 + (e >> 1)*8;
                    int cc = c0 + (e & 1);
                    smf[CSF + rr*37 + cc] =
                        acc[j][e] * smf[RNF+rr] * smf[RNF+36+cc] * 10.f;
                }
            }
        }
    }
    __syncthreads();
    if (t < 36) {
        smf[CSF + t*37 + 36] = smf[DUF + t];
        smf[CSF + 36*37 + t] = smf[DUF + 36 + t];
    }
    if (t == 0) smf[CSF + 36*37 + 36] = -1000.f;
    __syncthreads();

    for (int i = t; i < NP1; i += THREADS) smf[ECF + i] = __expf(smf[CSF + i]);
    __syncthreads();

    // ---- Sinkhorn: warps 0-1 only, named barrier ----
    if (t < 64) {
        const int m = t;
        const bool act = t < 37;
        const float lr = (m < 36) ? NORMC : LMD;
        #pragma unroll 1
        for (int it = 0; it < 20; ++it) {
            if (act) {
                const float* er = smf + ECF + m*37;
                float s0=0.f, s1=0.f, s2=0.f, s3=0.f;
                #pragma unroll
                for (int n = 0; n < 36; n += 4) {
                    s0 = fmaf(er[n+0], smf[EVF+n+0], s0);
                    s1 = fmaf(er[n+1], smf[EVF+n+1], s1);
                    s2 = fmaf(er[n+2], smf[EVF+n+2], s2);
                    s3 = fmaf(er[n+3], smf[EVF+n+3], s3);
                }
                s0 = fmaf(er[36], smf[EVF+36], s0);
                float uu = lr - __logf((s0+s1)+(s2+s3));
                smf[UF + m] = uu;
                smf[EUF + m] = __expf(uu);
            }
            asm volatile("bar.sync 5, 64;" ::: "memory");
            if (act) {
                const float* ecc = smf + ECF + m;
                float s0=0.f, s1=0.f, s2=0.f, s3=0.f;
                #pragma unroll
                for (int n = 0; n < 36; n += 4) {
                    s0 = fmaf(ecc[(n+0)*37], smf[EUF+n+0], s0);
                    s1 = fmaf(ecc[(n+1)*37], smf[EUF+n+1], s1);
                    s2 = fmaf(ecc[(n+2)*37], smf[EUF+n+2], s2);
                    s3 = fmaf(ecc[(n+3)*37], smf[EUF+n+3], s3);
                }
                s0 = fmaf(ecc[36*37], smf[EUF+36], s0);
                float vv = lr - __logf((s0+s1)+(s2+s3));
                smf[VF + m] = vv;
                smf[EVF + m] = __expf(vv);
            }
            asm volatile("bar.sync 5, 64;" ::: "memory");
        }
    }
    __syncthreads();

    // ---- epilogue: Z + total;  exp(Z) = 72 * ec * eu * ev ----
    float* ob = out + (size_t)b * NP1;
    float part = 0.f;
    for (int i = t; i < NP1; i += THREADS) {
        int mm = i / 37;
        int nn = i - mm*37;
        float cc = smf[CSF + i];
        ob[i] = cc + smf[UF + mm] + smf[VF + nn] - NORMC;
        if (mm < 36 && nn < 36)
            part += smf[ECF + i] * smf[EUF + mm] * smf[EVF + nn] * cc;
    }
    #pragma unroll
    for (int o = 16; o > 0; o >>= 1)
        part += __shfl_down_sync(0xffffffffu, part, o);
    if (lid == 0) atomicAdd(&smf[TOTF], part * 72.f);
    __syncthreads();
    if (t == 0) out[(size_t)B*NP1 + b] = smf[TOTF];
}

// ======================= launch =========================================
extern "C" void kernel_launch(void* const* d_in, const int* in_sizes, int n_in,
                              void* d_out, int out_size)
{
    const float* x  = (const float*)d_in[0];
    const float* y  = (const float*)d_in[1];
    const float* g  = (const float*)d_in[2];
    const float* bb = (const float*)d_in[3];
    const float* w  = (const float*)d_in[4];
    const float* bl = (const float*)d_in[5];
    const int B = in_sizes[0] / (36 * 768);
    float* out = (float*)d_out;

    cudaFuncSetAttribute(k_fused,
                         cudaFuncAttributeMaxDynamicSharedMemorySize, SM_BYTES);
    k_fused<<<B, THREADS, SM_BYTES>>>(x, y, g, bb, w, bl, out, B);
}

// round 11
// speedup vs baseline: 1.2882x; 1.2882x over previous
#include <cuda_runtime.h>
#include <cstdint>

#define THREADS 192
#define NCH 12              // 768 / 64 floats per chunk
#define NP1 1369

// ---- smem float offsets ----
#define AOF 0               // A stages: 2 * 3264 floats (48 rows x 68)
#define BOF 6528            // B stages: 2 * 2720 floats (40 rows x 68)
#define GWF 11968           // g*w vector, 768
#define WPF 12736           // 6 warps * 2
#define STF 12752           // stats partials 144*3 = 432
#define RNF 13184           // rsqrt norms 72
#define DUF 13256           // dustbin*10 72
#define UF  13328
#define VF  13365
#define EUF 13402
#define EVF 13439
#define TOTF 13476
#define SM_FLOATS 13504
#define SM_BYTES (SM_FLOATS*4)   // 54016 -> 4 CTAs/SM
// post-loop aliases (A stages dead after main loop)
#define CSF 0               // couplings 1369  (A stage 0)
#define ECF 3264            // exp couplings 1369 (A stage 1)

#define NORMC (-4.27666611901605529f)   // -log(72)
#define LMD   (-0.69314718055994531f)   // log(36)-log(72)

__device__ __forceinline__ void fma2(unsigned long long &d,
                                     unsigned long long a,
                                     unsigned long long b) {
    asm volatile("fma.rn.f32x2 %0, %1, %2, %0;" : "+l"(d) : "l"(a), "l"(b));
}
__device__ __forceinline__ float lo32(unsigned long long a){ return __uint_as_float((unsigned)a); }
__device__ __forceinline__ float hi32(unsigned long long a){ return __uint_as_float((unsigned)(a>>32)); }

__device__ __forceinline__ uint32_t f2tf(float f) {
    uint32_t u; asm("cvt.rna.tf32.f32 %0, %1;" : "=r"(u) : "f"(f)); return u;
}
__device__ __forceinline__ void mma1688(float* d, const uint32_t* a, const uint32_t* b) {
    asm volatile(
        "mma.sync.aligned.m16n8k8.row.col.f32.tf32.tf32.f32 "
        "{%0,%1,%2,%3}, {%4,%5,%6,%7}, {%8,%9}, {%0,%1,%2,%3};"
        : "+f"(d[0]), "+f"(d[1]), "+f"(d[2]), "+f"(d[3])
        : "r"(a[0]), "r"(a[1]), "r"(a[2]), "r"(a[3]), "r"(b[0]), "r"(b[1]));
}
__device__ __forceinline__ void cp16(uint32_t dst, const float* src) {
    asm volatile("cp.async.cg.shared.global [%0], [%1], 16;"
                 :: "r"(dst), "l"(src) : "memory");
}

// one 72-row x 64-float chunk: x rows -> A stage rows 0-35, y rows -> B rows 0-35
__device__ __forceinline__ void load_chunk(uint32_t smb, const float* xb,
                                           const float* yb, int c, int t) {
    uint32_t sA = smb + AOF*4 + (c&1)*13056;
    uint32_t sB = smb + BOF*4 + (c&1)*10880;
    #pragma unroll
    for (int r = 0; r < 6; ++r) {
        int op = t + THREADS*r;          // 0..1151, exact coverage
        int row = op >> 4, c4 = op & 15;
        if (row < 36)
            cp16(sA + row*272 + c4*16, xb + row*768 + c*64 + c4*4);
        else
            cp16(sB + (row-36)*272 + c4*16, yb + (row-36)*768 + c*64 + c4*4);
    }
    asm volatile("cp.async.commit_group;" ::: "memory");
}

// ======================= fused kernel ===================================
__global__ void __launch_bounds__(THREADS, 4)
k_fused(const float* __restrict__ X, const float* __restrict__ Y,
        const float* __restrict__ G, const float* __restrict__ Bln,
        const float* __restrict__ W, const float* __restrict__ Blin,
        float* __restrict__ out, int B)
{
    extern __shared__ __align__(16) float smf[];
    uint32_t smb;
    asm("{ .reg .u64 tt; cvta.to.shared.u64 tt, %1; cvt.u32.u64 %0, tt; }"
        : "=r"(smb) : "l"(smf));
    const int t = threadIdx.x;
    const int w = t >> 5, lid = t & 31;
    const int g = lid >> 2, tig = lid & 3;
    const int b = blockIdx.x;
    const float* xb = X + (size_t)b * 27648;
    const float* yb = Y + (size_t)b * 27648;

    // zero pad rows (A rows 36-47, B rows 36-39, both stages)
    for (int i = t; i < 16*68*2; i += THREADS) {
        int st = i / (16*68); int rem = i - st*(16*68);
        int row = rem / 68, col = rem - row*68;
        if (row < 12) smf[AOF + st*3264 + (36+row)*68 + col] = 0.f;
        else          smf[BOF + st*2720 + (24+row)*68 + col] = 0.f;
    }

    // prefetch chunk 0
    load_chunk(smb, xb, yb, 0, t);

    // g*w vector + warp partials (768 = 4 * 192, exact)
    {
        float sgw = 0.f, sbw = 0.f;
        #pragma unroll
        for (int r = 0; r < 4; ++r) {
            int h = t + THREADS*r;
            float wv = W[h];
            float gv = G[h]*wv;
            smf[GWF + h] = gv;
            sgw += gv;
            sbw += Bln[h]*wv;
        }
        #pragma unroll
        for (int o = 16; o > 0; o >>= 1) {
            sgw += __shfl_down_sync(0xffffffffu, sgw, o);
            sbw += __shfl_down_sync(0xffffffffu, sbw, o);
        }
        if (lid == 0) { smf[WPF + w*2] = sgw; smf[WPF + w*2 + 1] = sbw; }
    }

    // GEMM: all 6 warps.  warp = (mt = w>>1, nhalf = w&1)
    const int mt  = w >> 1;
    const int nh  = w & 1;
    const int nt0 = nh ? 3 : 0;
    const int ntn = nh ? 2 : 3;
    float acc[3][4];
    #pragma unroll
    for (int j = 0; j < 3; ++j)
        #pragma unroll
        for (int e = 0; e < 4; ++e) acc[j][e] = 0.f;

    // stats: one slice per thread for t<144 (slice s=t: row=s>>1, half=s&1)
    unsigned long long sx2 = 0ULL, sxx2 = 0ULL, sxg2 = 0ULL;
    const unsigned long long ONES2 = 0x3f8000003f800000ULL;
    const int srow = t >> 1, shalf = t & 1;

    #pragma unroll 1
    for (int c = 0; c < NCH; ++c) {
        asm volatile("cp.async.wait_group 0;" ::: "memory");
        __syncthreads();
        if (c + 1 < NCH) load_chunk(smb, xb, yb, c+1, t);

        // ---- tensor-core GEMM (exactly R7's inner loop) ----
        {
            const float* As = smf + AOF + (c&1)*3264 + (mt*16 + g)*68;
            const float* Bs = smf + BOF + (c&1)*2720 + (nt0*8 + g)*68;
            #pragma unroll
            for (int ks = 0; ks < 8; ++ks) {
                const int ko = ks*8 + tig;
                uint32_t a[4];
                a[0] = f2tf(As[ko]);
                a[1] = f2tf(As[8*68 + ko]);
                a[2] = f2tf(As[ko + 4]);
                a[3] = f2tf(As[8*68 + ko + 4]);
                #pragma unroll
                for (int j = 0; j < 3; ++j) {
                    if (j < ntn) {
                        const float* br = Bs + j*8*68 + ko;
                        uint32_t bf[2];
                        bf[0] = f2tf(br[0]);
                        bf[1] = f2tf(br[4]);
                        mma1688(acc[j], a, bf);
                    }
                }
            }
        }

        // ---- per-row stats, one slice/thread (overlaps MMA latency) ----
        if (t < 144) {
            const float* rp = smf + (srow < 36
                ? AOF + (c&1)*3264 + srow*68
                : BOF + (c&1)*2720 + (srow-36)*68) + shalf*32;
            const float* gp = smf + GWF + c*64 + shalf*32;
            #pragma unroll
            for (int j = 0; j < 8; ++j) {
                ulonglong2 v  = *reinterpret_cast<const ulonglong2*>(rp + j*4);
                ulonglong2 gg = *reinterpret_cast<const ulonglong2*>(gp + j*4);
                fma2(sx2,  v.x, ONES2);  fma2(sx2,  v.y, ONES2);
                fma2(sxx2, v.x, v.x);    fma2(sxx2, v.y, v.y);
                fma2(sxg2, v.x, gg.x);   fma2(sxg2, v.y, gg.y);
            }
        }
    }

    if (t < 144) {
        smf[STF + t*3 + 0] = lo32(sx2)  + hi32(sx2);
        smf[STF + t*3 + 1] = lo32(sxx2) + hi32(sxx2);
        smf[STF + t*3 + 2] = lo32(sxg2) + hi32(sxg2);
    }
    __syncthreads();    // main loop done; stage buffers dead -> aliases live

    // per-row finalize (72 rows)
    if (t < 72) {
        float Sx  = smf[STF + (2*t)*3 + 0] + smf[STF + (2*t+1)*3 + 0];
        float Sxx = smf[STF + (2*t)*3 + 1] + smf[STF + (2*t+1)*3 + 1];
        float Sxg = smf[STF + (2*t)*3 + 2] + smf[STF + (2*t+1)*3 + 2];
        float Sgw = 0.f, Sbw = 0.f;
        #pragma unroll
        for (int j = 0; j < 6; ++j) {
            Sgw += smf[WPF + j*2 + 0];
            Sbw += smf[WPF + j*2 + 1];
        }
        smf[RNF + t] = rsqrtf(Sxx);
        float mu  = Sx * (1.f/768.f);
        float var = Sxx * (1.f/768.f) - mu*mu;
        float rsd = rsqrtf(var + 1e-5f);
        smf[DUF + t] = tanhf((Sxg - mu*Sgw)*rsd + Sbw + Blin[0]) * 10.f;
    }
    if (t < 37) {
        smf[UF + t] = 0.f; smf[VF + t] = 0.f;
        smf[EUF + t] = 1.f; smf[EVF + t] = 1.f;
    }
    if (t == 0) smf[TOTF] = 0.f;
    __syncthreads();

    // write scaled couplings from MMA accumulators
    {
        #pragma unroll
        for (int j = 0; j < 3; ++j) {
            if (j < ntn) {
                int r0 = mt*16 + g;
                int c0 = (nt0 + j)*8 + 2*tig;
                #pragma unroll
                for (int e = 0; e < 4; ++e) {
                    int rr = r0 + (e >> 1)*8;
                    int cc = c0 + (e & 1);
                    if (rr < 36 && cc < 36)
                        smf[CSF + rr*37 + cc] =
                            acc[j][e] * smf[RNF+rr] * smf[RNF+36+cc] * 10.f;
                }
            }
        }
    }
    if (t < 36) {
        smf[CSF + t*37 + 36] = smf[DUF + t];
        smf[CSF + 36*37 + t] = smf[DUF + 36 + t];
    }
    if (t == 0) smf[CSF + 36*37 + 36] = -1000.f;
    __syncthreads();

    for (int i = t; i < NP1; i += THREADS) smf[ECF + i] = __expf(smf[CSF + i]);
    __syncthreads();

    // ---- Sinkhorn: warps 0-1 only, named barrier ----
    if (t < 64) {
        const int m = t;
        const bool act = t < 37;
        const float lr = (m < 36) ? NORMC : LMD;
        #pragma unroll 1
        for (int it = 0; it < 20; ++it) {
            if (act) {
                const float* er = smf + ECF + m*37;
                float s0=0.f, s1=0.f, s2=0.f, s3=0.f;
                #pragma unroll
                for (int n = 0; n < 36; n += 4) {
                    s0 = fmaf(er[n+0], smf[EVF+n+0], s0);
                    s1 = fmaf(er[n+1], smf[EVF+n+1], s1);
                    s2 = fmaf(er[n+2], smf[EVF+n+2], s2);
                    s3 = fmaf(er[n+3], smf[EVF+n+3], s3);
                }
                s0 = fmaf(er[36], smf[EVF+36], s0);
                float uu = lr - __logf((s0+s1)+(s2+s3));
                smf[UF + m] = uu;
                smf[EUF + m] = __expf(uu);
            }
            asm volatile("bar.sync 5, 64;" ::: "memory");
            if (act) {
                const float* ecc = smf + ECF + m;
                float s0=0.f, s1=0.f, s2=0.f, s3=0.f;
                #pragma unroll
                for (int n = 0; n < 36; n += 4) {
                    s0 = fmaf(ecc[(n+0)*37], smf[EUF+n+0], s0);
                    s1 = fmaf(ecc[(n+1)*37], smf[EUF+n+1], s1);
                    s2 = fmaf(ecc[(n+2)*37], smf[EUF+n+2], s2);
                    s3 = fmaf(ecc[(n+3)*37], smf[EUF+n+3], s3);
                }
                s0 = fmaf(ecc[36*37], smf[EUF+36], s0);
                float vv = lr - __logf((s0+s1)+(s2+s3));
                smf[VF + m] = vv;
                smf[EVF + m] = __expf(vv);
            }
            asm volatile("bar.sync 5, 64;" ::: "memory");
        }
    }
    __syncthreads();

    // ---- epilogue: Z + total;  exp(Z) = 72 * ec * eu * ev ----
    float* ob = out + (size_t)b * NP1;
    float part = 0.f;
    for (int i = t; i < NP1; i += THREADS) {
        int mm = i / 37;
        int nn = i - mm*37;
        float cc = smf[CSF + i];
        ob[i] = cc + smf[UF + mm] + smf[VF + nn] - NORMC;
        if (mm < 36 && nn < 36)
            part += smf[ECF + i] * smf[EUF + mm] * smf[EVF + nn] * cc;
    }
    #pragma unroll
    for (int o = 16; o > 0; o >>= 1)
        part += __shfl_down_sync(0xffffffffu, part, o);
    if (lid == 0) atomicAdd(&smf[TOTF], part * 72.f);
    __syncthreads();
    if (t == 0) out[(size_t)B*NP1 + b] = smf[TOTF];
}

// ======================= launch =========================================
extern "C" void kernel_launch(void* const* d_in, const int* in_sizes, int n_in,
                              void* d_out, int out_size)
{
    const float* x  = (const float*)d_in[0];
    const float* y  = (const float*)d_in[1];
    const float* g  = (const float*)d_in[2];
    const float* bb = (const float*)d_in[3];
    const float* w  = (const float*)d_in[4];
    const float* bl = (const float*)d_in[5];
    const int B = in_sizes[0] / (36 * 768);
    float* out = (float*)d_out;

    cudaFuncSetAttribute(k_fused,
                         cudaFuncAttributeMaxDynamicSharedMemorySize, SM_BYTES);
    k_fused<<<B, THREADS, SM_BYTES>>>(x, y, g, bb, w, bl, out, B);
}

// round 12
// speedup vs baseline: 1.4568x; 1.1309x over previous
#include <cuda_runtime.h>
#include <cstdint>

#define THREADS 192
#define NCH 12              // 768 / 64 floats per chunk
#define NP1 1369
#define RS 72               // row stride in floats (72 mod 32 = 8 -> conflict-free pairs)
#define ASTG (48*RS)        // 3456
#define BSTG (40*RS)        // 2880

// ---- smem float offsets ----
#define AOF 0               // A stages: 2 * 3456
#define BOF 6912            // B stages: 2 * 2880 -> ends 12672
#define GWF 12672           // g*w vector 768 -> 13440
#define WPF 13440           // 6 warp sbw partials (+pad 8) -> 13448
#define STF 13448           // sxx partials 144 -> 13592
#define SXF 13592           // row sums 72 -> 13664
#define SXGF 13664          // row (x.gw) 72 -> 13736
#define RNF 13736           // rsqrt norms 72 -> 13808
#define DUF 13808           // dustbin*10 72 -> 13880
#define UF  13880
#define VF  13917
#define EUF 13954
#define EVF 13991
#define TOTF 14028
#define SGWS 14029
#define SM_FLOATS 14032
#define SM_BYTES (SM_FLOATS*4)   // 56128 -> 4 CTAs/SM
// post-loop aliases (A stages dead after main loop)
#define CSF 0               // couplings 1369 (A stage 0)
#define ECF 3456            // exp couplings 1369 (A stage 1)

#define NORMC (-4.27666611901605529f)   // -log(72)
#define LMD   (-0.69314718055994531f)   // log(36)-log(72)

__device__ __forceinline__ void fma2(unsigned long long &d,
                                     unsigned long long a,
                                     unsigned long long b) {
    asm volatile("fma.rn.f32x2 %0, %1, %2, %0;" : "+l"(d) : "l"(a), "l"(b));
}
__device__ __forceinline__ float lo32(unsigned long long a){ return __uint_as_float((unsigned)a); }
__device__ __forceinline__ float hi32(unsigned long long a){ return __uint_as_float((unsigned)(a>>32)); }

__device__ __forceinline__ uint32_t f2tf(float f) {
    uint32_t u; asm("cvt.rna.tf32.f32 %0, %1;" : "=r"(u) : "f"(f)); return u;
}
__device__ __forceinline__ void mma1688(float* d, const uint32_t* a, const uint32_t* b) {
    asm volatile(
        "mma.sync.aligned.m16n8k8.row.col.f32.tf32.tf32.f32 "
        "{%0,%1,%2,%3}, {%4,%5,%6,%7}, {%8,%9}, {%0,%1,%2,%3};"
        : "+f"(d[0]), "+f"(d[1]), "+f"(d[2]), "+f"(d[3])
        : "r"(a[0]), "r"(a[1]), "r"(a[2]), "r"(a[3]), "r"(b[0]), "r"(b[1]));
}
__device__ __forceinline__ void cp16(uint32_t dst, const float* src) {
    asm volatile("cp.async.cg.shared.global [%0], [%1], 16;"
                 :: "r"(dst), "l"(src) : "memory");
}

// one 72-row x 64-float chunk: x rows -> A stage rows 0-35, y rows -> B rows 0-35
__device__ __forceinline__ void load_chunk(uint32_t smb, const float* xb,
                                           const float* yb, int c, int t) {
    uint32_t sA = smb + AOF*4 + (c&1)*(ASTG*4);
    uint32_t sB = smb + BOF*4 + (c&1)*(BSTG*4);
    #pragma unroll
    for (int r = 0; r < 6; ++r) {
        int op = t + THREADS*r;          // 0..1151 exact
        int row = op >> 4, c4 = op & 15;
        if (row < 36)
            cp16(sA + row*(RS*4) + c4*16, xb + row*768 + c*64 + c4*4);
        else
            cp16(sB + (row-36)*(RS*4) + c4*16, yb + (row-36)*768 + c*64 + c4*4);
    }
    asm volatile("cp.async.commit_group;" ::: "memory");
}

// ======================= fused kernel ===================================
__global__ void __launch_bounds__(THREADS, 4)
k_fused(const float* __restrict__ X, const float* __restrict__ Y,
        const float* __restrict__ G, const float* __restrict__ Bln,
        const float* __restrict__ W, const float* __restrict__ Blin,
        float* __restrict__ out, int B)
{
    extern __shared__ __align__(16) float smf[];
    uint32_t smb;
    asm("{ .reg .u64 tt; cvta.to.shared.u64 tt, %1; cvt.u32.u64 %0, tt; }"
        : "=r"(smb) : "l"(smf));
    const int t = threadIdx.x;
    const int w = t >> 5, lid = t & 31;
    const int g = lid >> 2, tig = lid & 3;
    const int b = blockIdx.x;
    const float* xb = X + (size_t)b * 27648;
    const float* yb = Y + (size_t)b * 27648;

    // init special rows, both stages: A rows 37..47 (ones,zeros), B rows 37..39
    // (row 37 = ones -> MMA computes row/col sums; rows 38+ = 0)
    for (int i = t; i < 2*14*64; i += THREADS) {
        int st = i / 896; int rem = i - st*896;
        int r = rem >> 6, col = rem & 63;
        float val = (r == 0 || r == 11) ? 1.f : 0.f;
        if (r < 11) smf[AOF + st*ASTG + (37+r)*RS + col] = val;
        else        smf[BOF + st*BSTG + (37+r-11)*RS + col] = val;
    }

    // prefetch chunk 0
    load_chunk(smb, xb, yb, 0, t);

    // g*w vector + per-warp sbw partial (768 = 4*192 exact)
    {
        float sbw = 0.f;
        float gv0 = 0.f;
        #pragma unroll
        for (int r = 0; r < 4; ++r) {
            int h = t + THREADS*r;
            float wv = W[h];
            float gv = G[h]*wv;
            smf[GWF + h] = gv;
            if (r == 0) gv0 = gv;
            sbw += Bln[h]*wv;
        }
        #pragma unroll
        for (int o = 16; o > 0; o >>= 1)
            sbw += __shfl_down_sync(0xffffffffu, sbw, o);
        if (lid == 0) smf[WPF + w] = sbw;
        // gw row (36) of stage 0 for chunk 0: thread t<64 owns gw[t]
        if (t < 64) {
            smf[AOF + 36*RS + t] = gv0;
            smf[BOF + 36*RS + t] = gv0;
        }
    }

    // GEMM: all 6 warps.  warp = (mt = w>>1, nhalf = w&1)
    const int mt  = w >> 1;
    const int nh  = w & 1;
    const int nt0 = nh ? 3 : 0;
    const int ntn = nh ? 2 : 3;
    float acc[3][4];
    #pragma unroll
    for (int j = 0; j < 3; ++j)
        #pragma unroll
        for (int e = 0; e < 4; ++e) acc[j][e] = 0.f;

    // stats: sxx only, one slice per thread for t<144
    unsigned long long sxx2 = 0ULL;
    const int srow = t >> 1, shalf = t & 1;

    #pragma unroll 1
    for (int c = 0; c < NCH; ++c) {
        asm volatile("cp.async.wait_group 0;" ::: "memory");
        __syncthreads();
        if (c + 1 < NCH) {
            load_chunk(smb, xb, yb, c+1, t);
            if (t < 64) {   // gw row for chunk c+1 (other buffer; read next phase)
                float gv = smf[GWF + (c+1)*64 + t];
                int s2 = (c+1)&1;
                smf[AOF + s2*ASTG + 36*RS + t] = gv;
                smf[BOF + s2*BSTG + 36*RS + t] = gv;
            }
        }

        // ---- tensor-core GEMM; k-paired LDS.64 fragments ----
        {
            const float* As = smf + AOF + (c&1)*ASTG + (mt*16 + g)*RS + 2*tig;
            const float* Bs = smf + BOF + (c&1)*BSTG + (nt0*8 + g)*RS + 2*tig;
            #pragma unroll
            for (int ks = 0; ks < 8; ++ks) {
                const int ko = ks*8;
                float2 aLo = *reinterpret_cast<const float2*>(As + ko);
                float2 aHi = *reinterpret_cast<const float2*>(As + 8*RS + ko);
                uint32_t a[4];
                a[0] = f2tf(aLo.x);
                a[1] = f2tf(aHi.x);
                a[2] = f2tf(aLo.y);
                a[3] = f2tf(aHi.y);
                #pragma unroll
                for (int j = 0; j < 3; ++j) {
                    if (j < ntn) {
                        float2 bb = *reinterpret_cast<const float2*>(
                            Bs + j*8*RS + ko);
                        uint32_t bf[2];
                        bf[0] = f2tf(bb.x);
                        bf[1] = f2tf(bb.y);
                        mma1688(acc[j], a, bf);
                    }
                }
            }
        }

        // ---- per-row sxx (overlaps MMA latency) ----
        if (t < 144) {
            const float* rp = smf + (srow < 36
                ? AOF + (c&1)*ASTG + srow*RS
                : BOF + (c&1)*BSTG + (srow-36)*RS) + shalf*32;
            #pragma unroll
            for (int j = 0; j < 8; ++j) {
                ulonglong2 v = *reinterpret_cast<const ulonglong2*>(rp + j*4);
                fma2(sxx2, v.x, v.x);
                fma2(sxx2, v.y, v.y);
            }
        }
    }

    if (t < 144) smf[STF + t] = lo32(sxx2) + hi32(sxx2);

    // ---- extract MMA-computed stats: col36 = x.gw, col37 = sum(x),
    //      row36 = gw.y, row37 = sum(y), (36,37) = sum(gw) ----
    #pragma unroll
    for (int j = 0; j < 3; ++j) {
        if (j < ntn) {
            int r0 = mt*16 + g;
            int c0 = (nt0 + j)*8 + 2*tig;
            #pragma unroll
            for (int e = 0; e < 4; ++e) {
                int rr = r0 + (e >> 1)*8;
                int cc = c0 + (e & 1);
                float val = acc[j][e];
                if (rr < 36) {
                    if (cc == 36)      smf[SXGF + rr] = val;
                    else if (cc == 37) smf[SXF + rr] = val;
                } else if (rr == 36) {
                    if (cc < 36)       smf[SXGF + 36 + cc] = val;
                    else if (cc == 37) smf[SGWS] = val;
                } else if (rr == 37 && cc < 36) {
                    smf[SXF + 36 + cc] = val;
                }
            }
        }
    }
    __syncthreads();    // main loop done; stage buffers dead -> aliases live

    // per-row finalize (72 rows)
    if (t < 72) {
        float Sxx = smf[STF + 2*t] + smf[STF + 2*t + 1];
        float Sx  = smf[SXF + t];
        float Sxg = smf[SXGF + t];
        float Sgw = smf[SGWS];
        float Sbw = 0.f;
        #pragma unroll
        for (int j = 0; j < 6; ++j) Sbw += smf[WPF + j];
        smf[RNF + t] = rsqrtf(Sxx);
        float mu  = Sx * (1.f/768.f);
        float var = Sxx * (1.f/768.f) - mu*mu;
        float rsd = rsqrtf(var + 1e-5f);
        smf[DUF + t] = tanhf((Sxg - mu*Sgw)*rsd + Sbw + Blin[0]) * 10.f;
    }
    if (t < 37) {
        smf[UF + t] = 0.f; smf[VF + t] = 0.f;
        smf[EUF + t] = 1.f; smf[EVF + t] = 1.f;
    }
    if (t == 0) smf[TOTF] = 0.f;
    __syncthreads();

    // write scaled couplings from MMA accumulators
    #pragma unroll
    for (int j = 0; j < 3; ++j) {
        if (j < ntn) {
            int r0 = mt*16 + g;
            int c0 = (nt0 + j)*8 + 2*tig;
            #pragma unroll
            for (int e = 0; e < 4; ++e) {
                int rr = r0 + (e >> 1)*8;
                int cc = c0 + (e & 1);
                if (rr < 36 && cc < 36)
                    smf[CSF + rr*37 + cc] =
                        acc[j][e] * smf[RNF+rr] * smf[RNF+36+cc] * 10.f;
            }
        }
    }
    if (t < 36) {
        smf[CSF + t*37 + 36] = smf[DUF + t];
        smf[CSF + 36*37 + t] = smf[DUF + 36 + t];
    }
    if (t == 0) smf[CSF + 36*37 + 36] = -1000.f;
    __syncthreads();

    for (int i = t; i < NP1; i += THREADS) smf[ECF + i] = __expf(smf[CSF + i]);
    __syncthreads();

    // ---- Sinkhorn: warps 0-1 only, named barrier ----
    if (t < 64) {
        const int m = t;
        const bool act = t < 37;
        const float lr = (m < 36) ? NORMC : LMD;
        #pragma unroll 1
        for (int it = 0; it < 20; ++it) {
            if (act) {
                const float* er = smf + ECF + m*37;
                float s0=0.f, s1=0.f, s2=0.f, s3=0.f;
                #pragma unroll
                for (int n = 0; n < 36; n += 4) {
                    s0 = fmaf(er[n+0], smf[EVF+n+0], s0);
                    s1 = fmaf(er[n+1], smf[EVF+n+1], s1);
                    s2 = fmaf(er[n+2], smf[EVF+n+2], s2);
                    s3 = fmaf(er[n+3], smf[EVF+n+3], s3);
                }
                s0 = fmaf(er[36], smf[EVF+36], s0);
                float uu = lr - __logf((s0+s1)+(s2+s3));
                smf[UF + m] = uu;
                smf[EUF + m] = __expf(uu);
            }
            asm volatile("bar.sync 5, 64;" ::: "memory");
            if (act) {
                const float* ecc = smf + ECF + m;
                float s0=0.f, s1=0.f, s2=0.f, s3=0.f;
                #pragma unroll
                for (int n = 0; n < 36; n += 4) {
                    s0 = fmaf(ecc[(n+0)*37], smf[EUF+n+0], s0);
                    s1 = fmaf(ecc[(n+1)*37], smf[EUF+n+1], s1);
                    s2 = fmaf(ecc[(n+2)*37], smf[EUF+n+2], s2);
                    s3 = fmaf(ecc[(n+3)*37], smf[EUF+n+3], s3);
                }
                s0 = fmaf(ecc[36*37], smf[EUF+36], s0);
                float vv = lr - __logf((s0+s1)+(s2+s3));
                smf[VF + m] = vv;
                smf[EVF + m] = __expf(vv);
            }
            asm volatile("bar.sync 5, 64;" ::: "memory");
        }
    }
    __syncthreads();

    // ---- epilogue: Z + total;  exp(Z) = 72 * ec * eu * ev ----
    float* ob = out + (size_t)b * NP1;
    float part = 0.f;
    for (int i = t; i < NP1; i += THREADS) {
        int mm = i / 37;
        int nn = i - mm*37;
        float cc = smf[CSF + i];
        ob[i] = cc + smf[UF + mm] + smf[VF + nn] - NORMC;
        if (mm < 36 && nn < 36)
            part += smf[ECF + i] * smf[EUF + mm] * smf[EVF + nn] * cc;
    }
    #pragma unroll
    for (int o = 16; o > 0; o >>= 1)
        part += __shfl_down_sync(0xffffffffu, part, o);
    if (lid == 0) atomicAdd(&smf[TOTF], part * 72.f);
    __syncthreads();
    if (t == 0) out[(size_t)B*NP1 + b] = smf[TOTF];
}

// ======================= launch =========================================
extern "C" void kernel_launch(void* const* d_in, const int* in_sizes, int n_in,
                              void* d_out, int out_size)
{
    const float* x  = (const float*)d_in[0];
    const float* y  = (const float*)d_in[1];
    const float* g  = (const float*)d_in[2];
    const float* bb = (const float*)d_in[3];
    const float* w  = (const float*)d_in[4];
    const float* bl = (const float*)d_in[5];
    const int B = in_sizes[0] / (36 * 768);
    float* out = (float*)d_out;

    cudaFuncSetAttribute(k_fused,
                         cudaFuncAttributeMaxDynamicSharedMemorySize, SM_BYTES);
    k_fused<<<B, THREADS, SM_BYTES>>>(x, y, g, bb, w, bl, out, B);
}